// round 2
// baseline (speedup 1.0000x reference)
#include <cuda_runtime.h>
#include <cuda_bf16.h>
#include <math.h>

// Problem constants
#define SEQ   2048
#define DMODEL 4096
#define NHEAD 32
#define NKV   8
#define HD    128
#define GQA   4            // NHEAD / NKV

// ---------------------------------------------------------------------------
// Scratch (device globals: allocation-free, zero-initialized at module load)
// ---------------------------------------------------------------------------
__device__ float g_Q[SEQ * DMODEL];              // 32 MB
__device__ float g_K[SEQ * NKV * HD];            // 8 MB
__device__ float g_V[SEQ * NKV * HD];            // 8 MB
__device__ float g_O[SEQ * DMODEL];              // 32 MB
__device__ float g_P[(size_t)NHEAD * SEQ * SEQ]; // 512 MB (per-head scores/probs)

// ---------------------------------------------------------------------------
// Generic row-major SGEMM: C[M,N] = A[M,K] @ B[K,N]
// 128x128 block, BK=8, 256 threads, 8x8 per-thread tile, float4 everywhere.
// All dims used are multiples of tile sizes -> no edge guards.
// ---------------------------------------------------------------------------
__global__ __launch_bounds__(256, 2)
void sgemm_nn(const float* __restrict__ A, const float* __restrict__ B,
              float* __restrict__ C, int K, int lda, int ldb, int ldc)
{
    constexpr int BM = 128, BN = 128, BK = 8;
    __shared__ float As[BK][BM];
    __shared__ float Bs[BK][BN];
    const int tid  = threadIdx.x;
    const int brow = blockIdx.y, bcol = blockIdx.x;
    const float* Ab = A + (size_t)brow * BM * lda;
    const float* Bb = B + bcol * BN;
    const int a_r = tid >> 1,  a_c = (tid & 1) * 4;   // A: 128 rows x 8 cols
    const int b_r = tid >> 5,  b_c = (tid & 31) * 4;  // B: 8 rows x 128 cols
    const int tr  = (tid >> 4) * 8, tc = (tid & 15) * 8;
    float acc[8][8] = {};
    for (int k0 = 0; k0 < K; k0 += BK) {
        float4 av = *reinterpret_cast<const float4*>(Ab + (size_t)a_r * lda + k0 + a_c);
        As[a_c + 0][a_r] = av.x; As[a_c + 1][a_r] = av.y;
        As[a_c + 2][a_r] = av.z; As[a_c + 3][a_r] = av.w;
        *reinterpret_cast<float4*>(&Bs[b_r][b_c]) =
            *reinterpret_cast<const float4*>(Bb + (size_t)(k0 + b_r) * ldb + b_c);
        __syncthreads();
#pragma unroll
        for (int kk = 0; kk < BK; kk++) {
            float ra[8], rb[8];
            *reinterpret_cast<float4*>(ra)     = *reinterpret_cast<const float4*>(&As[kk][tr]);
            *reinterpret_cast<float4*>(ra + 4) = *reinterpret_cast<const float4*>(&As[kk][tr + 4]);
            *reinterpret_cast<float4*>(rb)     = *reinterpret_cast<const float4*>(&Bs[kk][tc]);
            *reinterpret_cast<float4*>(rb + 4) = *reinterpret_cast<const float4*>(&Bs[kk][tc + 4]);
#pragma unroll
            for (int i = 0; i < 8; i++)
#pragma unroll
                for (int j = 0; j < 8; j++)
                    acc[i][j] += ra[i] * rb[j];
        }
        __syncthreads();
    }
    float* Cb = C + (size_t)(brow * BM + tr) * ldc + bcol * BN + tc;
#pragma unroll
    for (int i = 0; i < 8; i++) {
        *reinterpret_cast<float4*>(Cb + (size_t)i * ldc)     =
            make_float4(acc[i][0], acc[i][1], acc[i][2], acc[i][3]);
        *reinterpret_cast<float4*>(Cb + (size_t)i * ldc + 4) =
            make_float4(acc[i][4], acc[i][5], acc[i][6], acc[i][7]);
    }
}

// ---------------------------------------------------------------------------
// RoPE (interleaved pairs), angles in fp64 for accuracy. In-place.
// ---------------------------------------------------------------------------
__global__ void rope_kernel(float* __restrict__ X, int nheads, int ld, int total)
{
    int idx = blockIdx.x * blockDim.x + threadIdx.x;
    if (idx >= total) return;
    int p = idx & 63;
    int t = idx >> 6;
    int h = t % nheads;
    int s = t / nheads;
    double inv = exp(-((double)(2 * p) / (double)HD) * log(500000.0));
    double sv, cv;
    sincos((double)s * inv, &sv, &cv);
    float* q = X + (size_t)s * ld + h * HD + 2 * p;
    float x0 = q[0], x1 = q[1];
    q[0] = (float)((double)x0 * cv - (double)x1 * sv);
    q[1] = (float)((double)x0 * sv + (double)x1 * cv);
}

// ---------------------------------------------------------------------------
// Scores: per head h, S_h = Q_h @ K_{h/4}^T  (no scale; softmax applies it).
// NT form: both operands row-major [rows, 128], contract over HD=128.
// Tiles strictly above the diagonal are skipped (never read by softmax).
// ---------------------------------------------------------------------------
__global__ __launch_bounds__(256, 2)
void score_gemm(const float* __restrict__ Q, const float* __restrict__ Km,
                float* __restrict__ P)
{
    constexpr int BM = 128, BN = 128, BK = 8;
    const int brow = blockIdx.y, bcol = blockIdx.x, h = blockIdx.z;
    if (bcol > brow) return;  // fully masked tile
    const float* A = Q  + h * HD;            // lda = DMODEL
    const float* B = Km + (h >> 2) * HD;     // ldb = NKV*HD
    float* C = P + (size_t)h * SEQ * SEQ;    // ldc = SEQ
    const int tid = threadIdx.x;
    const int a_r = tid >> 1, a_c = (tid & 1) * 4;
    const int tr = (tid >> 4) * 8, tc = (tid & 15) * 8;
    __shared__ float As[BK][BM];
    __shared__ float Bs[BK][BN];
    float acc[8][8] = {};
    for (int k0 = 0; k0 < HD; k0 += BK) {
        float4 av = *reinterpret_cast<const float4*>(
            A + (size_t)(brow * BM + a_r) * DMODEL + k0 + a_c);
        As[a_c + 0][a_r] = av.x; As[a_c + 1][a_r] = av.y;
        As[a_c + 2][a_r] = av.z; As[a_c + 3][a_r] = av.w;
        float4 bv = *reinterpret_cast<const float4*>(
            B + (size_t)(bcol * BN + a_r) * (NKV * HD) + k0 + a_c);
        Bs[a_c + 0][a_r] = bv.x; Bs[a_c + 1][a_r] = bv.y;
        Bs[a_c + 2][a_r] = bv.z; Bs[a_c + 3][a_r] = bv.w;
        __syncthreads();
#pragma unroll
        for (int kk = 0; kk < BK; kk++) {
            float ra[8], rb[8];
            *reinterpret_cast<float4*>(ra)     = *reinterpret_cast<const float4*>(&As[kk][tr]);
            *reinterpret_cast<float4*>(ra + 4) = *reinterpret_cast<const float4*>(&As[kk][tr + 4]);
            *reinterpret_cast<float4*>(rb)     = *reinterpret_cast<const float4*>(&Bs[kk][tc]);
            *reinterpret_cast<float4*>(rb + 4) = *reinterpret_cast<const float4*>(&Bs[kk][tc + 4]);
#pragma unroll
            for (int i = 0; i < 8; i++)
#pragma unroll
                for (int j = 0; j < 8; j++)
                    acc[i][j] += ra[i] * rb[j];
        }
        __syncthreads();
    }
    float* Cb = C + (size_t)(brow * BM + tr) * SEQ + bcol * BN + tc;
#pragma unroll
    for (int i = 0; i < 8; i++) {
        *reinterpret_cast<float4*>(Cb + (size_t)i * SEQ)     =
            make_float4(acc[i][0], acc[i][1], acc[i][2], acc[i][3]);
        *reinterpret_cast<float4*>(Cb + (size_t)i * SEQ + 4) =
            make_float4(acc[i][4], acc[i][5], acc[i][6], acc[i][7]);
    }
}

// ---------------------------------------------------------------------------
// Causal softmax: one CTA per (row, head). Reads only cols [0, row] (so the
// masked region never needs NEG), applies scale, writes normalized probs and
// zero-fills cols (row, SEQ) so P@V can read rectangular tiles.
// ---------------------------------------------------------------------------
__global__ __launch_bounds__(128)
void softmax_causal(float* __restrict__ P)
{
    const int r = blockIdx.x, h = blockIdx.y;
    float* row = P + (size_t)h * SEQ * SEQ + (size_t)r * SEQ;
    const float scale = 0.08838834764831845f;  // 1/sqrt(128)
    const int tid = threadIdx.x;
    float vals[SEQ / 128];
    int cnt = 0;
    float m = -3.4e38f;
    for (int j = tid; j <= r; j += 128) {
        float v = row[j] * scale;
        vals[cnt++] = v;
        m = fmaxf(m, v);
    }
    __shared__ float red[4];
#pragma unroll
    for (int o = 16; o > 0; o >>= 1) m = fmaxf(m, __shfl_xor_sync(0xffffffffu, m, o));
    if ((tid & 31) == 0) red[tid >> 5] = m;
    __syncthreads();
    m = fmaxf(fmaxf(red[0], red[1]), fmaxf(red[2], red[3]));
    __syncthreads();
    float sum = 0.f;
    for (int i = 0; i < cnt; i++) {
        float e = expf(vals[i] - m);
        vals[i] = e;
        sum += e;
    }
#pragma unroll
    for (int o = 16; o > 0; o >>= 1) sum += __shfl_xor_sync(0xffffffffu, sum, o);
    if ((tid & 31) == 0) red[tid >> 5] = sum;
    __syncthreads();
    sum = red[0] + red[1] + red[2] + red[3];
    float rinv = 1.0f / sum;
    cnt = 0;
    for (int j = tid; j < SEQ; j += 128)
        row[j] = (j <= r) ? vals[cnt++] * rinv : 0.0f;
}

// ---------------------------------------------------------------------------
// O_h[2048,128] = P_h[2048,2048] @ V_{h/4}[2048,128], causal K-limit per row
// block (P is zero beyond the diagonal inside the last block).
// ---------------------------------------------------------------------------
__global__ __launch_bounds__(256, 2)
void pv_gemm(const float* __restrict__ P, const float* __restrict__ V,
             float* __restrict__ O)
{
    constexpr int BM = 128, BN = 128, BK = 8;
    const int h = blockIdx.z, brow = blockIdx.y;
    const float* A = P + (size_t)h * SEQ * SEQ;   // lda = SEQ
    const float* B = V + (h >> 2) * HD;           // ldb = NKV*HD
    float* C = O + h * HD;                        // ldc = DMODEL
    const int kmax = (brow + 1) * BM;             // causal: rows of V beyond block diag are all-zero P
    const int tid = threadIdx.x;
    const int a_r = tid >> 1, a_c = (tid & 1) * 4;
    const int b_r = tid >> 5, b_c = (tid & 31) * 4;
    const int tr = (tid >> 4) * 8, tc = (tid & 15) * 8;
    __shared__ float As[BK][BM];
    __shared__ float Bs[BK][BN];
    float acc[8][8] = {};
    const float* Ab = A + (size_t)brow * BM * SEQ;
    for (int k0 = 0; k0 < kmax; k0 += BK) {
        float4 av = *reinterpret_cast<const float4*>(Ab + (size_t)a_r * SEQ + k0 + a_c);
        As[a_c + 0][a_r] = av.x; As[a_c + 1][a_r] = av.y;
        As[a_c + 2][a_r] = av.z; As[a_c + 3][a_r] = av.w;
        *reinterpret_cast<float4*>(&Bs[b_r][b_c]) =
            *reinterpret_cast<const float4*>(B + (size_t)(k0 + b_r) * (NKV * HD) + b_c);
        __syncthreads();
#pragma unroll
        for (int kk = 0; kk < BK; kk++) {
            float ra[8], rb[8];
            *reinterpret_cast<float4*>(ra)     = *reinterpret_cast<const float4*>(&As[kk][tr]);
            *reinterpret_cast<float4*>(ra + 4) = *reinterpret_cast<const float4*>(&As[kk][tr + 4]);
            *reinterpret_cast<float4*>(rb)     = *reinterpret_cast<const float4*>(&Bs[kk][tc]);
            *reinterpret_cast<float4*>(rb + 4) = *reinterpret_cast<const float4*>(&Bs[kk][tc + 4]);
#pragma unroll
            for (int i = 0; i < 8; i++)
#pragma unroll
                for (int j = 0; j < 8; j++)
                    acc[i][j] += ra[i] * rb[j];
        }
        __syncthreads();
    }
    float* Cb = C + (size_t)(brow * BM + tr) * DMODEL + tc;
#pragma unroll
    for (int i = 0; i < 8; i++) {
        *reinterpret_cast<float4*>(Cb + (size_t)i * DMODEL)     =
            make_float4(acc[i][0], acc[i][1], acc[i][2], acc[i][3]);
        *reinterpret_cast<float4*>(Cb + (size_t)i * DMODEL + 4) =
            make_float4(acc[i][4], acc[i][5], acc[i][6], acc[i][7]);
    }
}

// ---------------------------------------------------------------------------
// Launch
// ---------------------------------------------------------------------------
extern "C" void kernel_launch(void* const* d_in, const int* in_sizes, int n_in,
                              void* d_out, int out_size)
{
    const float* x  = (const float*)d_in[0];
    const float* Wq = (const float*)d_in[1];
    const float* Wk = (const float*)d_in[2];
    const float* Wv = (const float*)d_in[3];
    const float* Wo = (const float*)d_in[4];
    float* out = (float*)d_out;

    float *Q, *K, *V, *O, *P;
    cudaGetSymbolAddress((void**)&Q, g_Q);
    cudaGetSymbolAddress((void**)&K, g_K);
    cudaGetSymbolAddress((void**)&V, g_V);
    cudaGetSymbolAddress((void**)&O, g_O);
    cudaGetSymbolAddress((void**)&P, g_P);

    // QKV projections
    sgemm_nn<<<dim3(DMODEL / 128, SEQ / 128), 256>>>(x, Wq, Q, DMODEL, DMODEL, DMODEL, DMODEL);
    sgemm_nn<<<dim3((NKV * HD) / 128, SEQ / 128), 256>>>(x, Wk, K, DMODEL, DMODEL, NKV * HD, NKV * HD);
    sgemm_nn<<<dim3((NKV * HD) / 128, SEQ / 128), 256>>>(x, Wv, V, DMODEL, DMODEL, NKV * HD, NKV * HD);

    // RoPE on Q and K
    {
        int totq = SEQ * NHEAD * (HD / 2);
        rope_kernel<<<(totq + 255) / 256, 256>>>(Q, NHEAD, DMODEL, totq);
        int totk = SEQ * NKV * (HD / 2);
        rope_kernel<<<(totk + 255) / 256, 256>>>(K, NKV, NKV * HD, totk);
    }

    // Scores (lower-triangular tiles only)
    score_gemm<<<dim3(SEQ / 128, SEQ / 128, NHEAD), 256>>>(Q, K, P);

    // Causal softmax (scale folded in; zero-fills masked region)
    softmax_causal<<<dim3(SEQ, NHEAD), 128>>>(P);

    // P @ V per head (causal K-limit)
    pv_gemm<<<dim3(1, SEQ / 128, NHEAD), 256>>>(P, V, O);

    // Output projection
    sgemm_nn<<<dim3(DMODEL / 128, SEQ / 128), 256>>>(O, Wo, out, DMODEL, DMODEL, DMODEL, DMODEL);
}

// round 3
// speedup vs baseline: 1.6457x; 1.6457x over previous
#include <cuda_runtime.h>
#include <cuda_bf16.h>
#include <mma.h>
#include <math.h>

using namespace nvcuda;

// Problem constants
#define SEQ    2048
#define DMODEL 4096
#define NHEAD  32
#define NKV    8
#define HD     128
#define KVD    (NKV * HD)   // 1024

// ---------------------------------------------------------------------------
// Scratch (device globals: allocation-free)
// ---------------------------------------------------------------------------
__device__ float g_Q[SEQ * DMODEL];              // 32 MB
__device__ float g_K[SEQ * KVD];                 // 8 MB
__device__ float g_V[SEQ * KVD];                 // 8 MB
__device__ float g_O[SEQ * DMODEL];              // 32 MB
__device__ float g_P[(size_t)NHEAD * SEQ * SEQ]; // 512 MB

// GEMM tiling
#define BM 128
#define BN 128
#define BKK 32
#define APAD 4
#define BPAD 4

typedef wmma::fragment<wmma::matrix_a, 16, 16, 8, wmma::precision::tf32, wmma::row_major> FragA;
typedef wmma::fragment<wmma::matrix_b, 16, 16, 8, wmma::precision::tf32, wmma::row_major> FragBr;
typedef wmma::fragment<wmma::matrix_b, 16, 16, 8, wmma::precision::tf32, wmma::col_major> FragBc;
typedef wmma::fragment<wmma::accumulator, 16, 16, 8, float> FragC;

// ---------------------------------------------------------------------------
// Generic row-major tf32 GEMM: C[M,N] = A[M,K] @ B[K,N]
// CTA 128x128, BK=32, 8 warps in 2x4 grid, warp tile 64x32 (4x2 wmma frags).
// Register-prefetch of next K-slab overlaps gmem latency with tensor work.
// ---------------------------------------------------------------------------
__global__ __launch_bounds__(256)
void gemm_tf32_nn(const float* __restrict__ A, const float* __restrict__ B,
                  float* __restrict__ C, int K, int lda, int ldb, int ldc)
{
    __shared__ float As[BM][BKK + APAD];
    __shared__ float Bs[BKK][BN + BPAD];
    const int tid = threadIdx.x;
    const int wid = tid >> 5;
    const int wm = wid >> 2, wn = wid & 3;
    const int brow = blockIdx.y, bcol = blockIdx.x;
    const int ar = tid >> 3, ac = (tid & 7) * 4;   // A: 32 rows/pass x 8 float4
    const int br = tid >> 5, bc = (tid & 31) * 4;  // B: 8 rows/pass x 32 float4
    const float* Ag = A + (size_t)(brow * BM) * lda;
    const float* Bg = B + bcol * BN;

    FragC acc[4][2];
#pragma unroll
    for (int i = 0; i < 4; i++)
#pragma unroll
        for (int j = 0; j < 2; j++) wmma::fill_fragment(acc[i][j], 0.0f);

    float4 pa[4], pb[4];
#pragma unroll
    for (int i = 0; i < 4; i++) {
        pa[i] = *reinterpret_cast<const float4*>(Ag + (size_t)(ar + 32 * i) * lda + ac);
        pb[i] = *reinterpret_cast<const float4*>(Bg + (size_t)(br + 8 * i) * ldb + bc);
    }
    for (int k0 = 0; k0 < K; k0 += BKK) {
#pragma unroll
        for (int i = 0; i < 4; i++) {
            *reinterpret_cast<float4*>(&As[ar + 32 * i][ac]) = pa[i];
            *reinterpret_cast<float4*>(&Bs[br + 8 * i][bc]) = pb[i];
        }
        __syncthreads();
        const int kn = k0 + BKK;
        if (kn < K) {
#pragma unroll
            for (int i = 0; i < 4; i++) {
                pa[i] = *reinterpret_cast<const float4*>(Ag + (size_t)(ar + 32 * i) * lda + kn + ac);
                pb[i] = *reinterpret_cast<const float4*>(Bg + (size_t)(kn + br + 8 * i) * ldb + bc);
            }
        }
#pragma unroll
        for (int kk = 0; kk < BKK; kk += 8) {
            FragA fa[4];
            FragBr fb[2];
#pragma unroll
            for (int i = 0; i < 4; i++) {
                wmma::load_matrix_sync(fa[i], &As[wm * 64 + i * 16][kk], BKK + APAD);
#pragma unroll
                for (int e = 0; e < fa[i].num_elements; e++)
                    fa[i].x[e] = wmma::__float_to_tf32(fa[i].x[e]);
            }
#pragma unroll
            for (int j = 0; j < 2; j++) {
                wmma::load_matrix_sync(fb[j], &Bs[kk][wn * 32 + j * 16], BN + BPAD);
#pragma unroll
                for (int e = 0; e < fb[j].num_elements; e++)
                    fb[j].x[e] = wmma::__float_to_tf32(fb[j].x[e]);
            }
#pragma unroll
            for (int i = 0; i < 4; i++)
#pragma unroll
                for (int j = 0; j < 2; j++)
                    wmma::mma_sync(acc[i][j], fa[i], fb[j], acc[i][j]);
        }
        __syncthreads();
    }
#pragma unroll
    for (int i = 0; i < 4; i++)
#pragma unroll
        for (int j = 0; j < 2; j++)
            wmma::store_matrix_sync(
                C + (size_t)(brow * BM + wm * 64 + i * 16) * ldc + bcol * BN + wn * 32 + j * 16,
                acc[i][j], ldc, wmma::mem_row_major);
}

// ---------------------------------------------------------------------------
// Scores: per head h, P_h = Q_h @ K_{h/4}^T.  B is K rows (col-major frag).
// Tiles strictly above the diagonal are skipped.
// ---------------------------------------------------------------------------
__global__ __launch_bounds__(256)
void score_tf32(const float* __restrict__ Q, const float* __restrict__ Km,
                float* __restrict__ P)
{
    const int brow = blockIdx.y, bcol = blockIdx.x, h = blockIdx.z;
    if (bcol > brow) return;
    __shared__ float As[BM][BKK + APAD];
    __shared__ float Bs[BN][BKK + APAD];   // Bs[n][k] -> col-major fragment, ld = BKK+APAD
    const int tid = threadIdx.x;
    const int wid = tid >> 5;
    const int wm = wid >> 2, wn = wid & 3;
    const int ar = tid >> 3, ac = (tid & 7) * 4;
    const float* Ag = Q + (size_t)(brow * BM) * DMODEL + h * HD;
    const float* Bg = Km + (size_t)(bcol * BN) * KVD + (h >> 2) * HD;

    FragC acc[4][2];
#pragma unroll
    for (int i = 0; i < 4; i++)
#pragma unroll
        for (int j = 0; j < 2; j++) wmma::fill_fragment(acc[i][j], 0.0f);

    float4 pa[4], pb[4];
#pragma unroll
    for (int i = 0; i < 4; i++) {
        pa[i] = *reinterpret_cast<const float4*>(Ag + (size_t)(ar + 32 * i) * DMODEL + ac);
        pb[i] = *reinterpret_cast<const float4*>(Bg + (size_t)(ar + 32 * i) * KVD + ac);
    }
    for (int k0 = 0; k0 < HD; k0 += BKK) {
#pragma unroll
        for (int i = 0; i < 4; i++) {
            *reinterpret_cast<float4*>(&As[ar + 32 * i][ac]) = pa[i];
            *reinterpret_cast<float4*>(&Bs[ar + 32 * i][ac]) = pb[i];
        }
        __syncthreads();
        const int kn = k0 + BKK;
        if (kn < HD) {
#pragma unroll
            for (int i = 0; i < 4; i++) {
                pa[i] = *reinterpret_cast<const float4*>(Ag + (size_t)(ar + 32 * i) * DMODEL + kn + ac);
                pb[i] = *reinterpret_cast<const float4*>(Bg + (size_t)(ar + 32 * i) * KVD + kn + ac);
            }
        }
#pragma unroll
        for (int kk = 0; kk < BKK; kk += 8) {
            FragA fa[4];
            FragBc fb[2];
#pragma unroll
            for (int i = 0; i < 4; i++) {
                wmma::load_matrix_sync(fa[i], &As[wm * 64 + i * 16][kk], BKK + APAD);
#pragma unroll
                for (int e = 0; e < fa[i].num_elements; e++)
                    fa[i].x[e] = wmma::__float_to_tf32(fa[i].x[e]);
            }
#pragma unroll
            for (int j = 0; j < 2; j++) {
                wmma::load_matrix_sync(fb[j], &Bs[wn * 32 + j * 16][kk], BKK + APAD);
#pragma unroll
                for (int e = 0; e < fb[j].num_elements; e++)
                    fb[j].x[e] = wmma::__float_to_tf32(fb[j].x[e]);
            }
#pragma unroll
            for (int i = 0; i < 4; i++)
#pragma unroll
                for (int j = 0; j < 2; j++)
                    wmma::mma_sync(acc[i][j], fa[i], fb[j], acc[i][j]);
        }
        __syncthreads();
    }
    float* Cb = P + (size_t)h * SEQ * SEQ;
#pragma unroll
    for (int i = 0; i < 4; i++)
#pragma unroll
        for (int j = 0; j < 2; j++)
            wmma::store_matrix_sync(
                Cb + (size_t)(brow * BM + wm * 64 + i * 16) * SEQ + bcol * BN + wn * 32 + j * 16,
                acc[i][j], SEQ, wmma::mem_row_major);
}

// ---------------------------------------------------------------------------
// O_h = P_h @ V_{h/4}, K-loop limited to causal extent (P zero-filled on the
// diagonal tile's upper part by softmax).
// ---------------------------------------------------------------------------
__global__ __launch_bounds__(256)
void pv_tf32(const float* __restrict__ P, const float* __restrict__ V,
             float* __restrict__ O)
{
    const int brow = blockIdx.y, h = blockIdx.z;
    const int kmax = (brow + 1) * BM;
    __shared__ float As[BM][BKK + APAD];
    __shared__ float Bs[BKK][BN + BPAD];
    const int tid = threadIdx.x;
    const int wid = tid >> 5;
    const int wm = wid >> 2, wn = wid & 3;
    const int ar = tid >> 3, ac = (tid & 7) * 4;
    const int br = tid >> 5, bc = (tid & 31) * 4;
    const float* Ag = P + (size_t)h * SEQ * SEQ + (size_t)(brow * BM) * SEQ;
    const float* Bg = V + (h >> 2) * HD;

    FragC acc[4][2];
#pragma unroll
    for (int i = 0; i < 4; i++)
#pragma unroll
        for (int j = 0; j < 2; j++) wmma::fill_fragment(acc[i][j], 0.0f);

    float4 pa[4], pb[4];
#pragma unroll
    for (int i = 0; i < 4; i++) {
        pa[i] = *reinterpret_cast<const float4*>(Ag + (size_t)(ar + 32 * i) * SEQ + ac);
        pb[i] = *reinterpret_cast<const float4*>(Bg + (size_t)(br + 8 * i) * KVD + bc);
    }
    for (int k0 = 0; k0 < kmax; k0 += BKK) {
#pragma unroll
        for (int i = 0; i < 4; i++) {
            *reinterpret_cast<float4*>(&As[ar + 32 * i][ac]) = pa[i];
            *reinterpret_cast<float4*>(&Bs[br + 8 * i][bc]) = pb[i];
        }
        __syncthreads();
        const int kn = k0 + BKK;
        if (kn < kmax) {
#pragma unroll
            for (int i = 0; i < 4; i++) {
                pa[i] = *reinterpret_cast<const float4*>(Ag + (size_t)(ar + 32 * i) * SEQ + kn + ac);
                pb[i] = *reinterpret_cast<const float4*>(Bg + (size_t)(kn + br + 8 * i) * KVD + bc);
            }
        }
#pragma unroll
        for (int kk = 0; kk < BKK; kk += 8) {
            FragA fa[4];
            FragBr fb[2];
#pragma unroll
            for (int i = 0; i < 4; i++) {
                wmma::load_matrix_sync(fa[i], &As[wm * 64 + i * 16][kk], BKK + APAD);
#pragma unroll
                for (int e = 0; e < fa[i].num_elements; e++)
                    fa[i].x[e] = wmma::__float_to_tf32(fa[i].x[e]);
            }
#pragma unroll
            for (int j = 0; j < 2; j++) {
                wmma::load_matrix_sync(fb[j], &Bs[kk][wn * 32 + j * 16], BN + BPAD);
#pragma unroll
                for (int e = 0; e < fb[j].num_elements; e++)
                    fb[j].x[e] = wmma::__float_to_tf32(fb[j].x[e]);
            }
#pragma unroll
            for (int i = 0; i < 4; i++)
#pragma unroll
                for (int j = 0; j < 2; j++)
                    wmma::mma_sync(acc[i][j], fa[i], fb[j], acc[i][j]);
        }
        __syncthreads();
    }
#pragma unroll
    for (int i = 0; i < 4; i++)
#pragma unroll
        for (int j = 0; j < 2; j++)
            wmma::store_matrix_sync(
                O + (size_t)(brow * BM + wm * 64 + i * 16) * DMODEL + h * HD + wn * 32 + j * 16,
                acc[i][j], DMODEL, wmma::mem_row_major);
}

// ---------------------------------------------------------------------------
// RoPE (interleaved pairs) — fp32. exp2f-based inv_freq: rel err ~1e-7,
// worst-case angle error ~3e-4 rad. In-place.
// ---------------------------------------------------------------------------
__global__ void rope_kernel(float* __restrict__ X, int nheads, int ld, int total)
{
    int idx = blockIdx.x * blockDim.x + threadIdx.x;
    if (idx >= total) return;
    int p = idx & 63;
    int t = idx >> 6;
    int h = t % nheads;
    int s = t / nheads;
    // inv_freq = 500000^(-p/64) = exp2(-(p/64) * log2(500000))
    float inv = exp2f(-(float)p * (18.931568569324174f / 64.0f));
    float sv, cv;
    sincosf((float)s * inv, &sv, &cv);
    float* q = X + (size_t)s * ld + h * HD + 2 * p;
    float x0 = q[0], x1 = q[1];
    q[0] = x0 * cv - x1 * sv;
    q[1] = x0 * sv + x1 * cv;
}

// ---------------------------------------------------------------------------
// Causal softmax: one CTA per (row, head). Reads cols [0,row], applies scale,
// writes normalized probs, zero-fills (row, SEQ).
// ---------------------------------------------------------------------------
__global__ __launch_bounds__(128)
void softmax_causal(float* __restrict__ P)
{
    const int r = blockIdx.x, h = blockIdx.y;
    float* row = P + (size_t)h * SEQ * SEQ + (size_t)r * SEQ;
    const float scale = 0.08838834764831845f;  // 1/sqrt(128)
    const int tid = threadIdx.x;
    float vals[SEQ / 128];
    int cnt = 0;
    float m = -3.4e38f;
    for (int j = tid; j <= r; j += 128) {
        float v = row[j] * scale;
        vals[cnt++] = v;
        m = fmaxf(m, v);
    }
    __shared__ float red[4];
#pragma unroll
    for (int o = 16; o > 0; o >>= 1) m = fmaxf(m, __shfl_xor_sync(0xffffffffu, m, o));
    if ((tid & 31) == 0) red[tid >> 5] = m;
    __syncthreads();
    m = fmaxf(fmaxf(red[0], red[1]), fmaxf(red[2], red[3]));
    __syncthreads();
    float sum = 0.f;
    for (int i = 0; i < cnt; i++) {
        float e = expf(vals[i] - m);
        vals[i] = e;
        sum += e;
    }
#pragma unroll
    for (int o = 16; o > 0; o >>= 1) sum += __shfl_xor_sync(0xffffffffu, sum, o);
    if ((tid & 31) == 0) red[tid >> 5] = sum;
    __syncthreads();
    sum = red[0] + red[1] + red[2] + red[3];
    float rinv = 1.0f / sum;
    cnt = 0;
    for (int j = tid; j < SEQ; j += 128)
        row[j] = (j <= r) ? vals[cnt++] * rinv : 0.0f;
}

// ---------------------------------------------------------------------------
// Launch
// ---------------------------------------------------------------------------
extern "C" void kernel_launch(void* const* d_in, const int* in_sizes, int n_in,
                              void* d_out, int out_size)
{
    const float* x  = (const float*)d_in[0];
    const float* Wq = (const float*)d_in[1];
    const float* Wk = (const float*)d_in[2];
    const float* Wv = (const float*)d_in[3];
    const float* Wo = (const float*)d_in[4];
    float* out = (float*)d_out;

    float *Q, *K, *V, *O, *P;
    cudaGetSymbolAddress((void**)&Q, g_Q);
    cudaGetSymbolAddress((void**)&K, g_K);
    cudaGetSymbolAddress((void**)&V, g_V);
    cudaGetSymbolAddress((void**)&O, g_O);
    cudaGetSymbolAddress((void**)&P, g_P);

    // QKV projections (tf32 tensor cores)
    gemm_tf32_nn<<<dim3(DMODEL / BN, SEQ / BM), 256>>>(x, Wq, Q, DMODEL, DMODEL, DMODEL, DMODEL);
    gemm_tf32_nn<<<dim3(KVD / BN, SEQ / BM), 256>>>(x, Wk, K, DMODEL, DMODEL, KVD, KVD);
    gemm_tf32_nn<<<dim3(KVD / BN, SEQ / BM), 256>>>(x, Wv, V, DMODEL, DMODEL, KVD, KVD);

    // RoPE on Q and K (fp32)
    {
        int totq = SEQ * NHEAD * (HD / 2);
        rope_kernel<<<(totq + 255) / 256, 256>>>(Q, NHEAD, DMODEL, totq);
        int totk = SEQ * NKV * (HD / 2);
        rope_kernel<<<(totk + 255) / 256, 256>>>(K, NKV, KVD, totk);
    }

    // Scores (lower-triangular tiles only)
    score_tf32<<<dim3(SEQ / BN, SEQ / BM, NHEAD), 256>>>(Q, K, P);

    // Causal softmax
    softmax_causal<<<dim3(SEQ, NHEAD), 128>>>(P);

    // P @ V per head (causal K-limit)
    pv_tf32<<<dim3(1, SEQ / BM, NHEAD), 256>>>(P, V, O);

    // Output projection
    gemm_tf32_nn<<<dim3(DMODEL / BN, SEQ / BM), 256>>>(O, Wo, out, DMODEL, DMODEL, DMODEL, DMODEL);
}

// round 9
// speedup vs baseline: 2.1572x; 1.3108x over previous
#include <cuda_runtime.h>
#include <cuda_bf16.h>
#include <mma.h>
#include <math.h>

using namespace nvcuda;

// Problem constants
#define SEQ    2048
#define DMODEL 4096
#define NHEAD  32
#define NKV    8
#define HD     128
#define KVD    (NKV * HD)   // 1024

// ---------------------------------------------------------------------------
// Scratch (device globals: allocation-free)
// ---------------------------------------------------------------------------
__device__ float g_Q[SEQ * DMODEL];              // 32 MB
__device__ float g_K[SEQ * KVD];                 // 8 MB
__device__ float g_V[SEQ * KVD];                 // 8 MB
__device__ float g_O[SEQ * DMODEL];              // 32 MB

// GEMM tiling
#define BM 128
#define BN 128
#define BKK 32

typedef wmma::fragment<wmma::matrix_a, 16, 16, 8, wmma::precision::tf32, wmma::row_major> FragA;
typedef wmma::fragment<wmma::matrix_b, 16, 16, 8, wmma::precision::tf32, wmma::row_major> FragBr;
typedef wmma::fragment<wmma::accumulator, 16, 16, 8, float> FragC;

// ---------------------------------------------------------------------------
// Small PTX helpers
// ---------------------------------------------------------------------------
__device__ __forceinline__ void cp_async16(void* dst, const void* src) {
    unsigned s = (unsigned)__cvta_generic_to_shared(dst);
    asm volatile("cp.async.cg.shared.global [%0], [%1], 16;" :: "r"(s), "l"(src));
}
__device__ __forceinline__ void cp_commit() {
    asm volatile("cp.async.commit_group;");
}
__device__ __forceinline__ unsigned f2tf32(float f) {
    unsigned u; asm("cvt.rna.tf32.f32 %0, %1;" : "=r"(u) : "f"(f)); return u;
}
__device__ __forceinline__ void mma_tf32(float* c, const unsigned* a, unsigned b0, unsigned b1) {
    asm volatile(
        "mma.sync.aligned.m16n8k8.row.col.f32.tf32.tf32.f32 "
        "{%0,%1,%2,%3}, {%4,%5,%6,%7}, {%8,%9}, {%0,%1,%2,%3};"
        : "+f"(c[0]), "+f"(c[1]), "+f"(c[2]), "+f"(c[3])
        : "r"(a[0]), "r"(a[1]), "r"(a[2]), "r"(a[3]), "r"(b0), "r"(b1));
}

// ---------------------------------------------------------------------------
// Generic row-major tf32 GEMM: C[M,N] = A[M,K] @ B[K,N]
// 128x128 CTA tile, BK=32, 2-stage cp.async double buffer, 8 warps (2x4),
// warp tile 64x32 (4x2 wmma m16n16k8 frags).
// ---------------------------------------------------------------------------
struct GemmSmem {
    float As[2][BM][BKK + 4];   // row stride 36 floats (144B, 16B-aligned)
    float Bs[2][BKK][BN + 4];   // row stride 132 floats (528B)
};

__global__ __launch_bounds__(256)
void gemm_tf32_nn(const float* __restrict__ A, const float* __restrict__ B,
                  float* __restrict__ C, int K, int lda, int ldb, int ldc)
{
    extern __shared__ char smem_raw[];
    GemmSmem& sm = *reinterpret_cast<GemmSmem*>(smem_raw);
    const int tid = threadIdx.x;
    const int wid = tid >> 5;
    const int wm = wid >> 2, wn = wid & 3;
    const int brow = blockIdx.y, bcol = blockIdx.x;
    const float* Ag = A + (size_t)(brow * BM) * lda;
    const float* Bg = B + bcol * BN;

    FragC acc[4][2];
#pragma unroll
    for (int i = 0; i < 4; i++)
#pragma unroll
        for (int j = 0; j < 2; j++) wmma::fill_fragment(acc[i][j], 0.0f);

    auto stage = [&](int s, int k0) {
#pragma unroll
        for (int i = 0; i < 4; i++) {              // A: 128 rows x 8 16B-chunks
            int ch = tid + 256 * i;
            int r = ch >> 3, c = (ch & 7) << 2;
            cp_async16(&sm.As[s][r][c], Ag + (size_t)r * lda + k0 + c);
        }
#pragma unroll
        for (int i = 0; i < 4; i++) {              // B: 32 rows x 32 16B-chunks
            int ch = tid + 256 * i;
            int r = ch >> 5, c = (ch & 31) << 2;
            cp_async16(&sm.Bs[s][r][c], Bg + (size_t)(k0 + r) * ldb + c);
        }
        cp_commit();
    };

    const int nt = K / BKK;
    stage(0, 0);
    for (int t = 0; t < nt; t++) {
        if (t + 1 < nt) {
            stage((t + 1) & 1, (t + 1) * BKK);
            asm volatile("cp.async.wait_group 1;");
        } else {
            asm volatile("cp.async.wait_group 0;");
        }
        __syncthreads();
        const int s = t & 1;
#pragma unroll
        for (int kk = 0; kk < BKK; kk += 8) {
            FragA fa[4];
            FragBr fb[2];
#pragma unroll
            for (int i = 0; i < 4; i++) {
                wmma::load_matrix_sync(fa[i], &sm.As[s][wm * 64 + i * 16][kk], BKK + 4);
#pragma unroll
                for (int e = 0; e < fa[i].num_elements; e++)
                    fa[i].x[e] = wmma::__float_to_tf32(fa[i].x[e]);
            }
#pragma unroll
            for (int j = 0; j < 2; j++) {
                wmma::load_matrix_sync(fb[j], &sm.Bs[s][kk][wn * 32 + j * 16], BN + 4);
#pragma unroll
                for (int e = 0; e < fb[j].num_elements; e++)
                    fb[j].x[e] = wmma::__float_to_tf32(fb[j].x[e]);
            }
#pragma unroll
            for (int i = 0; i < 4; i++)
#pragma unroll
                for (int j = 0; j < 2; j++)
                    wmma::mma_sync(acc[i][j], fa[i], fb[j], acc[i][j]);
        }
        __syncthreads();
    }
#pragma unroll
    for (int i = 0; i < 4; i++)
#pragma unroll
        for (int j = 0; j < 2; j++)
            wmma::store_matrix_sync(
                C + (size_t)(brow * BM + wm * 64 + i * 16) * ldc + bcol * BN + wn * 32 + j * 16,
                acc[i][j], ldc, wmma::mem_row_major);
}

// ---------------------------------------------------------------------------
// Flash attention (causal, GQA). One CTA = 64 query rows x 1 head.
// 4 warps, each owns 16 rows. Online softmax entirely in registers using the
// documented mma.m16n8k8 fragment layouts. K/V tiles (64x128) via cp.async.
// P round-trips through a per-warp smem strip to re-fragment for the PV mma.
// ---------------------------------------------------------------------------
struct FlashSmem {
    float Ks[64][132];   // row stride 528B (16B-aligned)
    float Vs[64][136];   // row stride 544B
    float Ps[64][68];    // per-warp 16-row strips
};

__global__ __launch_bounds__(128)
void flash_attn(const float* __restrict__ Q, const float* __restrict__ Kg,
                const float* __restrict__ Vg, float* __restrict__ O)
{
    extern __shared__ char smem_raw[];
    FlashSmem& sm = *reinterpret_cast<FlashSmem*>(smem_raw);

    const int h   = blockIdx.x;
    const int qb  = gridDim.y - 1 - blockIdx.y;   // big workloads first
    const int kvh = h >> 2;
    const int warp = threadIdx.x >> 5;
    const int lane = threadIdx.x & 31;
    const int lr = lane >> 2;   // 0..7
    const int lc = lane & 3;    // 0..3

    // --- load Q fragments (scale folded in), kept in registers all kernel ---
    unsigned qa[16][4];
    {
        const float scale = 0.08838834764831845f;   // 1/sqrt(128)
        const float* Qb = Q + (size_t)(qb * 64 + warp * 16) * DMODEL + h * HD;
#pragma unroll
        for (int kt = 0; kt < 16; kt++) {
            qa[kt][0] = f2tf32(Qb[(size_t)lr * DMODEL + kt * 8 + lc] * scale);
            qa[kt][1] = f2tf32(Qb[(size_t)(lr + 8) * DMODEL + kt * 8 + lc] * scale);
            qa[kt][2] = f2tf32(Qb[(size_t)lr * DMODEL + kt * 8 + lc + 4] * scale);
            qa[kt][3] = f2tf32(Qb[(size_t)(lr + 8) * DMODEL + kt * 8 + lc + 4] * scale);
        }
    }

    float oacc[16][4];
#pragma unroll
    for (int j = 0; j < 16; j++)
#pragma unroll
        for (int e = 0; e < 4; e++) oacc[j][e] = 0.0f;
    float m0 = -1e30f, m1 = -1e30f, l0 = 0.0f, l1 = 0.0f;

    for (int kb = 0; kb <= qb; kb++) {
        __syncthreads();   // all warps done with previous Ks/Vs
        {
            const float* Kt = Kg + (size_t)(kb * 64) * KVD + kvh * HD;
            const float* Vt = Vg + (size_t)(kb * 64) * KVD + kvh * HD;
            // FIX: full tile = 64 rows x 128 floats = 2048 16B-chunks each.
            // 128 threads x 16 iterations; r = ch/32 (0..63), c = (ch%32)*4.
#pragma unroll
            for (int i = 0; i < 16; i++) {
                int ch = threadIdx.x + 128 * i;
                int r = ch >> 5, c = (ch & 31) << 2;
                cp_async16(&sm.Ks[r][c], Kt + (size_t)r * KVD + c);
                cp_async16(&sm.Vs[r][c], Vt + (size_t)r * KVD + c);
            }
            cp_commit();
            asm volatile("cp.async.wait_group 0;");
        }
        __syncthreads();

        // ---- S = (Q*scale) @ K^T  [16 x 64] per warp ----
        float sacc[8][4];
#pragma unroll
        for (int j = 0; j < 8; j++)
#pragma unroll
            for (int e = 0; e < 4; e++) sacc[j][e] = 0.0f;
#pragma unroll
        for (int kt = 0; kt < 16; kt++) {
#pragma unroll
            for (int j = 0; j < 8; j++) {
                unsigned b0 = f2tf32(sm.Ks[j * 8 + lr][kt * 8 + lc]);
                unsigned b1 = f2tf32(sm.Ks[j * 8 + lr][kt * 8 + lc + 4]);
                mma_tf32(sacc[j], qa[kt], b0, b1);
            }
        }

        // ---- causal mask (diagonal block only) ----
        if (kb == qb) {
            const int r0 = warp * 16 + lr, r1 = r0 + 8;
#pragma unroll
            for (int j = 0; j < 8; j++) {
                int c0 = j * 8 + lc * 2;
                if (c0     > r0) sacc[j][0] = -1e30f;
                if (c0 + 1 > r0) sacc[j][1] = -1e30f;
                if (c0     > r1) sacc[j][2] = -1e30f;
                if (c0 + 1 > r1) sacc[j][3] = -1e30f;
            }
        }

        // ---- online softmax (rows r0 = lane/4, r1 = r0+8 of warp strip) ----
        float mx0 = -1e30f, mx1 = -1e30f;
#pragma unroll
        for (int j = 0; j < 8; j++) {
            mx0 = fmaxf(mx0, fmaxf(sacc[j][0], sacc[j][1]));
            mx1 = fmaxf(mx1, fmaxf(sacc[j][2], sacc[j][3]));
        }
        mx0 = fmaxf(mx0, __shfl_xor_sync(0xffffffffu, mx0, 1));
        mx0 = fmaxf(mx0, __shfl_xor_sync(0xffffffffu, mx0, 2));
        mx1 = fmaxf(mx1, __shfl_xor_sync(0xffffffffu, mx1, 1));
        mx1 = fmaxf(mx1, __shfl_xor_sync(0xffffffffu, mx1, 2));
        const float mn0 = fmaxf(m0, mx0), mn1 = fmaxf(m1, mx1);
        const float al0 = __expf(m0 - mn0), al1 = __expf(m1 - mn1);
        m0 = mn0; m1 = mn1;

        float s0 = 0.0f, s1 = 0.0f;
        const int prow = warp * 16 + lr;
#pragma unroll
        for (int j = 0; j < 8; j++) {
            float p0 = __expf(sacc[j][0] - m0);
            float p1 = __expf(sacc[j][1] - m0);
            float p2 = __expf(sacc[j][2] - m1);
            float p3 = __expf(sacc[j][3] - m1);
            s0 += p0 + p1;
            s1 += p2 + p3;
            *reinterpret_cast<float2*>(&sm.Ps[prow][j * 8 + lc * 2]) = make_float2(p0, p1);
            *reinterpret_cast<float2*>(&sm.Ps[prow + 8][j * 8 + lc * 2]) = make_float2(p2, p3);
        }
        s0 += __shfl_xor_sync(0xffffffffu, s0, 1);
        s0 += __shfl_xor_sync(0xffffffffu, s0, 2);
        s1 += __shfl_xor_sync(0xffffffffu, s1, 1);
        s1 += __shfl_xor_sync(0xffffffffu, s1, 2);
        l0 = l0 * al0 + s0;
        l1 = l1 * al1 + s1;

        // rescale O accumulator (row mapping of C frags matches m0/m1 rows)
#pragma unroll
        for (int j = 0; j < 16; j++) {
            oacc[j][0] *= al0; oacc[j][1] *= al0;
            oacc[j][2] *= al1; oacc[j][3] *= al1;
        }
        __syncwarp();

        // ---- O += P @ V  (A from per-warp Ps strip, B from Vs) ----
#pragma unroll
        for (int kt = 0; kt < 8; kt++) {
            unsigned pa[4];
            pa[0] = f2tf32(sm.Ps[warp * 16 + lr][kt * 8 + lc]);
            pa[1] = f2tf32(sm.Ps[warp * 16 + lr + 8][kt * 8 + lc]);
            pa[2] = f2tf32(sm.Ps[warp * 16 + lr][kt * 8 + lc + 4]);
            pa[3] = f2tf32(sm.Ps[warp * 16 + lr + 8][kt * 8 + lc + 4]);
#pragma unroll
            for (int j = 0; j < 16; j++) {
                unsigned b0 = f2tf32(sm.Vs[kt * 8 + lc][j * 8 + lr]);
                unsigned b1 = f2tf32(sm.Vs[kt * 8 + lc + 4][j * 8 + lr]);
                mma_tf32(oacc[j], pa, b0, b1);
            }
        }
    }

    // ---- epilogue: normalize and store ----
    const float r0 = 1.0f / l0, r1 = 1.0f / l1;
    float* Ob = O + (size_t)(qb * 64 + warp * 16) * DMODEL + h * HD;
#pragma unroll
    for (int j = 0; j < 16; j++) {
        *reinterpret_cast<float2*>(&Ob[(size_t)lr * DMODEL + j * 8 + lc * 2]) =
            make_float2(oacc[j][0] * r0, oacc[j][1] * r0);
        *reinterpret_cast<float2*>(&Ob[(size_t)(lr + 8) * DMODEL + j * 8 + lc * 2]) =
            make_float2(oacc[j][2] * r1, oacc[j][3] * r1);
    }
}

// ---------------------------------------------------------------------------
// RoPE (interleaved pairs), fp32, in-place.
// ---------------------------------------------------------------------------
__global__ void rope_kernel(float* __restrict__ X, int nheads, int ld, int total)
{
    int idx = blockIdx.x * blockDim.x + threadIdx.x;
    if (idx >= total) return;
    int p = idx & 63;
    int t = idx >> 6;
    int h = t % nheads;
    int s = t / nheads;
    float inv = exp2f(-(float)p * (18.931568569324174f / 64.0f));
    float sv, cv;
    sincosf((float)s * inv, &sv, &cv);
    float* q = X + (size_t)s * ld + h * HD + 2 * p;
    float x0 = q[0], x1 = q[1];
    q[0] = x0 * cv - x1 * sv;
    q[1] = x0 * sv + x1 * cv;
}

// ---------------------------------------------------------------------------
// Launch
// ---------------------------------------------------------------------------
extern "C" void kernel_launch(void* const* d_in, const int* in_sizes, int n_in,
                              void* d_out, int out_size)
{
    const float* x  = (const float*)d_in[0];
    const float* Wq = (const float*)d_in[1];
    const float* Wk = (const float*)d_in[2];
    const float* Wv = (const float*)d_in[3];
    const float* Wo = (const float*)d_in[4];
    float* out = (float*)d_out;

    float *Q, *K, *V, *O;
    cudaGetSymbolAddress((void**)&Q, g_Q);
    cudaGetSymbolAddress((void**)&K, g_K);
    cudaGetSymbolAddress((void**)&V, g_V);
    cudaGetSymbolAddress((void**)&O, g_O);

    cudaFuncSetAttribute(gemm_tf32_nn, cudaFuncAttributeMaxDynamicSharedMemorySize,
                         (int)sizeof(GemmSmem));
    cudaFuncSetAttribute(flash_attn, cudaFuncAttributeMaxDynamicSharedMemorySize,
                         (int)sizeof(FlashSmem));

    // QKV projections
    gemm_tf32_nn<<<dim3(DMODEL / BN, SEQ / BM), 256, sizeof(GemmSmem)>>>(
        x, Wq, Q, DMODEL, DMODEL, DMODEL, DMODEL);
    gemm_tf32_nn<<<dim3(KVD / BN, SEQ / BM), 256, sizeof(GemmSmem)>>>(
        x, Wk, K, DMODEL, DMODEL, KVD, KVD);
    gemm_tf32_nn<<<dim3(KVD / BN, SEQ / BM), 256, sizeof(GemmSmem)>>>(
        x, Wv, V, DMODEL, DMODEL, KVD, KVD);

    // RoPE
    {
        int totq = SEQ * NHEAD * (HD / 2);
        rope_kernel<<<(totq + 255) / 256, 256>>>(Q, NHEAD, DMODEL, totq);
        int totk = SEQ * NKV * (HD / 2);
        rope_kernel<<<(totk + 255) / 256, 256>>>(K, NKV, KVD, totk);
    }

    // Fused causal flash attention -> O
    flash_attn<<<dim3(NHEAD, SEQ / 64), 128, sizeof(FlashSmem)>>>(Q, K, V, O);

    // Output projection
    gemm_tf32_nn<<<dim3(DMODEL / BN, SEQ / BM), 256, sizeof(GemmSmem)>>>(
        O, Wo, out, DMODEL, DMODEL, DMODEL, DMODEL);
}

// round 11
// speedup vs baseline: 7.1861x; 3.3312x over previous
#include <cuda_runtime.h>
#include <cuda_bf16.h>
#include <cuda_fp16.h>
#include <mma.h>
#include <math.h>

using namespace nvcuda;

// Problem constants
#define SEQ    2048
#define DMODEL 4096
#define NHEAD  32
#define NKV    8
#define HD     128
#define KVD    (NKV * HD)   // 1024

// ---------------------------------------------------------------------------
// Scratch (device globals: allocation-free)
// ---------------------------------------------------------------------------
__device__ float g_Q[SEQ * DMODEL];              // 32 MB
__device__ float g_K[SEQ * KVD];                 // 8 MB
__device__ float g_V[SEQ * KVD];                 // 8 MB
__device__ float g_O[SEQ * DMODEL];              // 32 MB
__device__ __half g_x16[SEQ * DMODEL];           // 16 MB
__device__ __half g_O16[SEQ * DMODEL];           // 16 MB
__device__ __half g_Wq16[DMODEL * DMODEL];       // 32 MB
__device__ __half g_Wk16[DMODEL * KVD];          // 8 MB
__device__ __half g_Wv16[DMODEL * KVD];          // 8 MB
__device__ __half g_Wo16[DMODEL * DMODEL];       // 32 MB

// ---------------------------------------------------------------------------
// PTX helpers
// ---------------------------------------------------------------------------
__device__ __forceinline__ void cp_async16(void* dst, const void* src) {
    unsigned s = (unsigned)__cvta_generic_to_shared(dst);
    asm volatile("cp.async.cg.shared.global [%0], [%1], 16;" :: "r"(s), "l"(src));
}
__device__ __forceinline__ void cp_commit() {
    asm volatile("cp.async.commit_group;");
}
__device__ __forceinline__ unsigned f2tf32(float f) {
    unsigned u; asm("cvt.rna.tf32.f32 %0, %1;" : "=r"(u) : "f"(f)); return u;
}
__device__ __forceinline__ void mma_tf32(float* c, const unsigned* a, unsigned b0, unsigned b1) {
    asm volatile(
        "mma.sync.aligned.m16n8k8.row.col.f32.tf32.tf32.f32 "
        "{%0,%1,%2,%3}, {%4,%5,%6,%7}, {%8,%9}, {%0,%1,%2,%3};"
        : "+f"(c[0]), "+f"(c[1]), "+f"(c[2]), "+f"(c[3])
        : "r"(a[0]), "r"(a[1]), "r"(a[2]), "r"(a[3]), "r"(b0), "r"(b1));
}

// ---------------------------------------------------------------------------
// Bulk fp32 -> fp16 conversion (vectorized, 8 elems/thread)
// ---------------------------------------------------------------------------
__global__ void f32_to_f16(const float* __restrict__ in, __half* __restrict__ out, int n)
{
    int i = (blockIdx.x * blockDim.x + threadIdx.x) * 8;
    if (i >= n) return;
    float4 a = *reinterpret_cast<const float4*>(in + i);
    float4 b = *reinterpret_cast<const float4*>(in + i + 4);
    __half2 h[4];
    h[0] = __floats2half2_rn(a.x, a.y);
    h[1] = __floats2half2_rn(a.z, a.w);
    h[2] = __floats2half2_rn(b.x, b.y);
    h[3] = __floats2half2_rn(b.z, b.w);
    *reinterpret_cast<uint4*>(out + i) = *reinterpret_cast<uint4*>(h);
}

// ---------------------------------------------------------------------------
// fp16 GEMM with fp32 accumulate: C[M,N] = A[M,K] @ B[K,N]  (row-major all)
// 128x128 CTA tile, BK=32, 2-stage cp.async, 8 warps (2x4), warp tile 64x32.
// wmma m16n16k16 half frags -> LDSM fragment loads, HMMA.16816 compute.
// fp16 mantissa == tf32 mantissa (10 bits) and accum is fp32, so precision
// is statistically identical to the tf32 path this replaces.
// ---------------------------------------------------------------------------
typedef wmma::fragment<wmma::matrix_a, 16, 16, 16, __half, wmma::row_major> HFragA;
typedef wmma::fragment<wmma::matrix_b, 16, 16, 16, __half, wmma::row_major> HFragB;
typedef wmma::fragment<wmma::accumulator, 16, 16, 16, float> HFragC;

struct GemmHSmem {
    __half As[2][128][40];   // row stride 80B: LDSM-conflict-free mod 128B
    __half Bs[2][32][136];   // row stride 272B: conflict-free
};

__global__ __launch_bounds__(256)
void gemm_f16_nn(const __half* __restrict__ A, const __half* __restrict__ B,
                 float* __restrict__ C, int K, int lda, int ldb, int ldc)
{
    extern __shared__ char smem_raw[];
    GemmHSmem& sm = *reinterpret_cast<GemmHSmem*>(smem_raw);
    const int tid = threadIdx.x;
    const int wid = tid >> 5;
    const int wm = wid >> 2, wn = wid & 3;
    const int brow = blockIdx.y, bcol = blockIdx.x;
    const __half* Ag = A + (size_t)(brow * 128) * lda;
    const __half* Bg = B + bcol * 128;

    HFragC acc[4][2];
#pragma unroll
    for (int i = 0; i < 4; i++)
#pragma unroll
        for (int j = 0; j < 2; j++) wmma::fill_fragment(acc[i][j], 0.0f);

    auto stage = [&](int s, int k0) {
        // A: 128 rows x 4 chunks (8 halves = 16B) = 512 chunks
#pragma unroll
        for (int i = 0; i < 2; i++) {
            int ch = tid + 256 * i;
            int r = ch >> 2, c = (ch & 3) * 8;
            cp_async16(&sm.As[s][r][c], Ag + (size_t)r * lda + k0 + c);
        }
        // B: 32 rows x 16 chunks = 512 chunks
#pragma unroll
        for (int i = 0; i < 2; i++) {
            int ch = tid + 256 * i;
            int r = ch >> 4, c = (ch & 15) * 8;
            cp_async16(&sm.Bs[s][r][c], Bg + (size_t)(k0 + r) * ldb + c);
        }
        cp_commit();
    };

    const int nt = K / 32;
    stage(0, 0);
    for (int t = 0; t < nt; t++) {
        if (t + 1 < nt) {
            stage((t + 1) & 1, (t + 1) * 32);
            asm volatile("cp.async.wait_group 1;");
        } else {
            asm volatile("cp.async.wait_group 0;");
        }
        __syncthreads();
        const int s = t & 1;
#pragma unroll
        for (int kk = 0; kk < 32; kk += 16) {
            HFragA fa[4];
            HFragB fb[2];
#pragma unroll
            for (int i = 0; i < 4; i++)
                wmma::load_matrix_sync(fa[i], &sm.As[s][wm * 64 + i * 16][kk], 40);
#pragma unroll
            for (int j = 0; j < 2; j++)
                wmma::load_matrix_sync(fb[j], &sm.Bs[s][kk][wn * 32 + j * 16], 136);
#pragma unroll
            for (int i = 0; i < 4; i++)
#pragma unroll
                for (int j = 0; j < 2; j++)
                    wmma::mma_sync(acc[i][j], fa[i], fb[j], acc[i][j]);
        }
        __syncthreads();
    }
#pragma unroll
    for (int i = 0; i < 4; i++)
#pragma unroll
        for (int j = 0; j < 2; j++)
            wmma::store_matrix_sync(
                C + (size_t)(brow * 128 + wm * 64 + i * 16) * ldc + bcol * 128 + wn * 32 + j * 16,
                acc[i][j], ldc, wmma::mem_row_major);
}

// ---------------------------------------------------------------------------
// Flash attention (causal, GQA) — unchanged from the passing R9 kernel.
// One CTA = 64 query rows x 1 head; tf32 mma; online softmax in registers.
// ---------------------------------------------------------------------------
struct FlashSmem {
    float Ks[64][132];
    float Vs[64][136];
    float Ps[64][68];
};

__global__ __launch_bounds__(128)
void flash_attn(const float* __restrict__ Q, const float* __restrict__ Kg,
                const float* __restrict__ Vg, float* __restrict__ O)
{
    extern __shared__ char smem_raw[];
    FlashSmem& sm = *reinterpret_cast<FlashSmem*>(smem_raw);

    const int h   = blockIdx.x;
    const int qb  = gridDim.y - 1 - blockIdx.y;
    const int kvh = h >> 2;
    const int warp = threadIdx.x >> 5;
    const int lane = threadIdx.x & 31;
    const int lr = lane >> 2;
    const int lc = lane & 3;

    unsigned qa[16][4];
    {
        const float scale = 0.08838834764831845f;   // 1/sqrt(128)
        const float* Qb = Q + (size_t)(qb * 64 + warp * 16) * DMODEL + h * HD;
#pragma unroll
        for (int kt = 0; kt < 16; kt++) {
            qa[kt][0] = f2tf32(Qb[(size_t)lr * DMODEL + kt * 8 + lc] * scale);
            qa[kt][1] = f2tf32(Qb[(size_t)(lr + 8) * DMODEL + kt * 8 + lc] * scale);
            qa[kt][2] = f2tf32(Qb[(size_t)lr * DMODEL + kt * 8 + lc + 4] * scale);
            qa[kt][3] = f2tf32(Qb[(size_t)(lr + 8) * DMODEL + kt * 8 + lc + 4] * scale);
        }
    }

    float oacc[16][4];
#pragma unroll
    for (int j = 0; j < 16; j++)
#pragma unroll
        for (int e = 0; e < 4; e++) oacc[j][e] = 0.0f;
    float m0 = -1e30f, m1 = -1e30f, l0 = 0.0f, l1 = 0.0f;

    for (int kb = 0; kb <= qb; kb++) {
        __syncthreads();
        {
            const float* Kt = Kg + (size_t)(kb * 64) * KVD + kvh * HD;
            const float* Vt = Vg + (size_t)(kb * 64) * KVD + kvh * HD;
#pragma unroll
            for (int i = 0; i < 16; i++) {
                int ch = threadIdx.x + 128 * i;
                int r = ch >> 5, c = (ch & 31) << 2;
                cp_async16(&sm.Ks[r][c], Kt + (size_t)r * KVD + c);
                cp_async16(&sm.Vs[r][c], Vt + (size_t)r * KVD + c);
            }
            cp_commit();
            asm volatile("cp.async.wait_group 0;");
        }
        __syncthreads();

        float sacc[8][4];
#pragma unroll
        for (int j = 0; j < 8; j++)
#pragma unroll
            for (int e = 0; e < 4; e++) sacc[j][e] = 0.0f;
#pragma unroll
        for (int kt = 0; kt < 16; kt++) {
#pragma unroll
            for (int j = 0; j < 8; j++) {
                unsigned b0 = f2tf32(sm.Ks[j * 8 + lr][kt * 8 + lc]);
                unsigned b1 = f2tf32(sm.Ks[j * 8 + lr][kt * 8 + lc + 4]);
                mma_tf32(sacc[j], qa[kt], b0, b1);
            }
        }

        if (kb == qb) {
            const int r0 = warp * 16 + lr, r1 = r0 + 8;
#pragma unroll
            for (int j = 0; j < 8; j++) {
                int c0 = j * 8 + lc * 2;
                if (c0     > r0) sacc[j][0] = -1e30f;
                if (c0 + 1 > r0) sacc[j][1] = -1e30f;
                if (c0     > r1) sacc[j][2] = -1e30f;
                if (c0 + 1 > r1) sacc[j][3] = -1e30f;
            }
        }

        float mx0 = -1e30f, mx1 = -1e30f;
#pragma unroll
        for (int j = 0; j < 8; j++) {
            mx0 = fmaxf(mx0, fmaxf(sacc[j][0], sacc[j][1]));
            mx1 = fmaxf(mx1, fmaxf(sacc[j][2], sacc[j][3]));
        }
        mx0 = fmaxf(mx0, __shfl_xor_sync(0xffffffffu, mx0, 1));
        mx0 = fmaxf(mx0, __shfl_xor_sync(0xffffffffu, mx0, 2));
        mx1 = fmaxf(mx1, __shfl_xor_sync(0xffffffffu, mx1, 1));
        mx1 = fmaxf(mx1, __shfl_xor_sync(0xffffffffu, mx1, 2));
        const float mn0 = fmaxf(m0, mx0), mn1 = fmaxf(m1, mx1);
        const float al0 = __expf(m0 - mn0), al1 = __expf(m1 - mn1);
        m0 = mn0; m1 = mn1;

        float s0 = 0.0f, s1 = 0.0f;
        const int prow = warp * 16 + lr;
#pragma unroll
        for (int j = 0; j < 8; j++) {
            float p0 = __expf(sacc[j][0] - m0);
            float p1 = __expf(sacc[j][1] - m0);
            float p2 = __expf(sacc[j][2] - m1);
            float p3 = __expf(sacc[j][3] - m1);
            s0 += p0 + p1;
            s1 += p2 + p3;
            *reinterpret_cast<float2*>(&sm.Ps[prow][j * 8 + lc * 2]) = make_float2(p0, p1);
            *reinterpret_cast<float2*>(&sm.Ps[prow + 8][j * 8 + lc * 2]) = make_float2(p2, p3);
        }
        s0 += __shfl_xor_sync(0xffffffffu, s0, 1);
        s0 += __shfl_xor_sync(0xffffffffu, s0, 2);
        s1 += __shfl_xor_sync(0xffffffffu, s1, 1);
        s1 += __shfl_xor_sync(0xffffffffu, s1, 2);
        l0 = l0 * al0 + s0;
        l1 = l1 * al1 + s1;

#pragma unroll
        for (int j = 0; j < 16; j++) {
            oacc[j][0] *= al0; oacc[j][1] *= al0;
            oacc[j][2] *= al1; oacc[j][3] *= al1;
        }
        __syncwarp();

#pragma unroll
        for (int kt = 0; kt < 8; kt++) {
            unsigned pa[4];
            pa[0] = f2tf32(sm.Ps[warp * 16 + lr][kt * 8 + lc]);
            pa[1] = f2tf32(sm.Ps[warp * 16 + lr + 8][kt * 8 + lc]);
            pa[2] = f2tf32(sm.Ps[warp * 16 + lr][kt * 8 + lc + 4]);
            pa[3] = f2tf32(sm.Ps[warp * 16 + lr + 8][kt * 8 + lc + 4]);
#pragma unroll
            for (int j = 0; j < 16; j++) {
                unsigned b0 = f2tf32(sm.Vs[kt * 8 + lc][j * 8 + lr]);
                unsigned b1 = f2tf32(sm.Vs[kt * 8 + lc + 4][j * 8 + lr]);
                mma_tf32(oacc[j], pa, b0, b1);
            }
        }
    }

    const float r0 = 1.0f / l0, r1 = 1.0f / l1;
    float* Ob = O + (size_t)(qb * 64 + warp * 16) * DMODEL + h * HD;
#pragma unroll
    for (int j = 0; j < 16; j++) {
        *reinterpret_cast<float2*>(&Ob[(size_t)lr * DMODEL + j * 8 + lc * 2]) =
            make_float2(oacc[j][0] * r0, oacc[j][1] * r0);
        *reinterpret_cast<float2*>(&Ob[(size_t)(lr + 8) * DMODEL + j * 8 + lc * 2]) =
            make_float2(oacc[j][2] * r1, oacc[j][3] * r1);
    }
}

// ---------------------------------------------------------------------------
// RoPE (interleaved pairs), fp32, in-place.
// ---------------------------------------------------------------------------
__global__ void rope_kernel(float* __restrict__ X, int nheads, int ld, int total)
{
    int idx = blockIdx.x * blockDim.x + threadIdx.x;
    if (idx >= total) return;
    int p = idx & 63;
    int t = idx >> 6;
    int h = t % nheads;
    int s = t / nheads;
    float inv = exp2f(-(float)p * (18.931568569324174f / 64.0f));
    float sv, cv;
    sincosf((float)s * inv, &sv, &cv);
    float* q = X + (size_t)s * ld + h * HD + 2 * p;
    float x0 = q[0], x1 = q[1];
    q[0] = x0 * cv - x1 * sv;
    q[1] = x0 * sv + x1 * cv;
}

// ---------------------------------------------------------------------------
// Launch
// ---------------------------------------------------------------------------
extern "C" void kernel_launch(void* const* d_in, const int* in_sizes, int n_in,
                              void* d_out, int out_size)
{
    const float* x  = (const float*)d_in[0];
    const float* Wq = (const float*)d_in[1];
    const float* Wk = (const float*)d_in[2];
    const float* Wv = (const float*)d_in[3];
    const float* Wo = (const float*)d_in[4];
    float* out = (float*)d_out;

    float *Q, *K, *V, *O;
    __half *x16, *O16, *Wq16, *Wk16, *Wv16, *Wo16;
    cudaGetSymbolAddress((void**)&Q, g_Q);
    cudaGetSymbolAddress((void**)&K, g_K);
    cudaGetSymbolAddress((void**)&V, g_V);
    cudaGetSymbolAddress((void**)&O, g_O);
    cudaGetSymbolAddress((void**)&x16, g_x16);
    cudaGetSymbolAddress((void**)&O16, g_O16);
    cudaGetSymbolAddress((void**)&Wq16, g_Wq16);
    cudaGetSymbolAddress((void**)&Wk16, g_Wk16);
    cudaGetSymbolAddress((void**)&Wv16, g_Wv16);
    cudaGetSymbolAddress((void**)&Wo16, g_Wo16);

    cudaFuncSetAttribute(gemm_f16_nn, cudaFuncAttributeMaxDynamicSharedMemorySize,
                         (int)sizeof(GemmHSmem));
    cudaFuncSetAttribute(flash_attn, cudaFuncAttributeMaxDynamicSharedMemorySize,
                         (int)sizeof(FlashSmem));

    // fp32 -> fp16 conversions (x and weights)
    {
        const int nx = SEQ * DMODEL;
        const int nq = DMODEL * DMODEL;
        const int nk = DMODEL * KVD;
        f32_to_f16<<<(nx / 8 + 255) / 256, 256>>>(x,  x16,  nx);
        f32_to_f16<<<(nq / 8 + 255) / 256, 256>>>(Wq, Wq16, nq);
        f32_to_f16<<<(nk / 8 + 255) / 256, 256>>>(Wk, Wk16, nk);
        f32_to_f16<<<(nk / 8 + 255) / 256, 256>>>(Wv, Wv16, nk);
        f32_to_f16<<<(nq / 8 + 255) / 256, 256>>>(Wo, Wo16, nq);
    }

    // QKV projections (fp16 HMMA, fp32 accumulate)
    gemm_f16_nn<<<dim3(DMODEL / 128, SEQ / 128), 256, sizeof(GemmHSmem)>>>(
        x16, Wq16, Q, DMODEL, DMODEL, DMODEL, DMODEL);
    gemm_f16_nn<<<dim3(KVD / 128, SEQ / 128), 256, sizeof(GemmHSmem)>>>(
        x16, Wk16, K, DMODEL, DMODEL, KVD, KVD);
    gemm_f16_nn<<<dim3(KVD / 128, SEQ / 128), 256, sizeof(GemmHSmem)>>>(
        x16, Wv16, V, DMODEL, DMODEL, KVD, KVD);

    // RoPE
    {
        int totq = SEQ * NHEAD * (HD / 2);
        rope_kernel<<<(totq + 255) / 256, 256>>>(Q, NHEAD, DMODEL, totq);
        int totk = SEQ * NKV * (HD / 2);
        rope_kernel<<<(totk + 255) / 256, 256>>>(K, NKV, KVD, totk);
    }

    // Fused causal flash attention -> O (fp32)
    flash_attn<<<dim3(NHEAD, SEQ / 64), 128, sizeof(FlashSmem)>>>(Q, K, V, O);

    // O -> fp16, then output projection
    {
        const int no = SEQ * DMODEL;
        f32_to_f16<<<(no / 8 + 255) / 256, 256>>>(O, O16, no);
    }
    gemm_f16_nn<<<dim3(DMODEL / 128, SEQ / 128), 256, sizeof(GemmHSmem)>>>(
        O16, Wo16, out, DMODEL, DMODEL, DMODEL, DMODEL);
}

// round 14
// speedup vs baseline: 8.4512x; 1.1760x over previous
#include <cuda_runtime.h>
#include <cuda_fp16.h>
#include <mma.h>
#include <math.h>
#include <stdint.h>

using namespace nvcuda;

// Problem constants
#define SEQ    2048
#define DMODEL 4096
#define NHEAD  32
#define NKV    8
#define HD     128
#define KVD    (NKV * HD)   // 1024

// ---------------------------------------------------------------------------
// Scratch (device globals: allocation-free)
// ---------------------------------------------------------------------------
__device__ float  g_Q[SEQ * DMODEL];           // fp32 Q (rope in-place; flash reads)
__device__ float  g_K[SEQ * KVD];              // fp32 K (pre-rope)
__device__ float  g_V[SEQ * KVD];              // fp32 V
__device__ __half g_K16[SEQ * KVD];            // roped K, fp16, [s][kv]
__device__ __half g_V16T[KVD * SEQ];           // V transposed, fp16, [kv][s]
__device__ __half g_x16[SEQ * DMODEL];
__device__ __half g_O16[SEQ * DMODEL];         // flash output, fp16
__device__ __half g_Wq16[DMODEL * DMODEL];
__device__ __half g_Wk16[DMODEL * KVD];
__device__ __half g_Wv16[DMODEL * KVD];
__device__ __half g_Wo16[DMODEL * DMODEL];

// ---------------------------------------------------------------------------
// PTX helpers
// ---------------------------------------------------------------------------
__device__ __forceinline__ void cp_async16(void* dst, const void* src) {
    unsigned s = (unsigned)__cvta_generic_to_shared(dst);
    asm volatile("cp.async.cg.shared.global [%0], [%1], 16;" :: "r"(s), "l"(src));
}
__device__ __forceinline__ void cp_commit() {
    asm volatile("cp.async.commit_group;");
}
__device__ __forceinline__ void mma_f16(float* c, const unsigned* a, unsigned b0, unsigned b1) {
    asm volatile(
        "mma.sync.aligned.m16n8k16.row.col.f32.f16.f16.f32 "
        "{%0,%1,%2,%3}, {%4,%5,%6,%7}, {%8,%9}, {%0,%1,%2,%3};"
        : "+f"(c[0]), "+f"(c[1]), "+f"(c[2]), "+f"(c[3])
        : "r"(a[0]), "r"(a[1]), "r"(a[2]), "r"(a[3]), "r"(b0), "r"(b1));
}
__device__ __forceinline__ unsigned packh2(float a, float b) {
    __half2 h = __floats2half2_rn(a, b);
    return *reinterpret_cast<unsigned*>(&h);
}

// ---------------------------------------------------------------------------
// Bulk fp32 -> fp16 conversion
// ---------------------------------------------------------------------------
__global__ void f32_to_f16(const float* __restrict__ in, __half* __restrict__ out, int n)
{
    int i = (blockIdx.x * blockDim.x + threadIdx.x) * 8;
    if (i >= n) return;
    float4 a = *reinterpret_cast<const float4*>(in + i);
    float4 b = *reinterpret_cast<const float4*>(in + i + 4);
    __half2 h[4];
    h[0] = __floats2half2_rn(a.x, a.y);
    h[1] = __floats2half2_rn(a.z, a.w);
    h[2] = __floats2half2_rn(b.x, b.y);
    h[3] = __floats2half2_rn(b.z, b.w);
    *reinterpret_cast<uint4*>(out + i) = *reinterpret_cast<uint4*>(h);
}

// ---------------------------------------------------------------------------
// V transpose + convert: V[S][KVD] fp32 -> V16T[KVD][S] fp16
// ---------------------------------------------------------------------------
__global__ void v_transp16(const float* __restrict__ in, __half* __restrict__ out)
{
    __shared__ float t[32][33];
    int c0 = blockIdx.x * 32, s0 = blockIdx.y * 32;
    int tx = threadIdx.x, ty = threadIdx.y;   // 32 x 8
#pragma unroll
    for (int i = 0; i < 32; i += 8)
        t[ty + i][tx] = in[(size_t)(s0 + ty + i) * KVD + c0 + tx];
    __syncthreads();
#pragma unroll
    for (int i = 0; i < 32; i += 8)
        out[(size_t)(c0 + ty + i) * SEQ + s0 + tx] = __float2half(t[tx][ty + i]);
}

// ---------------------------------------------------------------------------
// fp16 GEMM with fp32 accumulate — unchanged from passing R11 kernel.
// ---------------------------------------------------------------------------
typedef wmma::fragment<wmma::matrix_a, 16, 16, 16, __half, wmma::row_major> HFragA;
typedef wmma::fragment<wmma::matrix_b, 16, 16, 16, __half, wmma::row_major> HFragB;
typedef wmma::fragment<wmma::accumulator, 16, 16, 16, float> HFragC;

struct GemmHSmem {
    __half As[2][128][40];
    __half Bs[2][32][136];
};

__global__ __launch_bounds__(256)
void gemm_f16_nn(const __half* __restrict__ A, const __half* __restrict__ B,
                 float* __restrict__ C, int K, int lda, int ldb, int ldc)
{
    extern __shared__ char smem_raw[];
    GemmHSmem& sm = *reinterpret_cast<GemmHSmem*>(smem_raw);
    const int tid = threadIdx.x;
    const int wid = tid >> 5;
    const int wm = wid >> 2, wn = wid & 3;
    const int brow = blockIdx.y, bcol = blockIdx.x;
    const __half* Ag = A + (size_t)(brow * 128) * lda;
    const __half* Bg = B + bcol * 128;

    HFragC acc[4][2];
#pragma unroll
    for (int i = 0; i < 4; i++)
#pragma unroll
        for (int j = 0; j < 2; j++) wmma::fill_fragment(acc[i][j], 0.0f);

    auto stage = [&](int s, int k0) {
#pragma unroll
        for (int i = 0; i < 2; i++) {
            int ch = tid + 256 * i;
            int r = ch >> 2, c = (ch & 3) * 8;
            cp_async16(&sm.As[s][r][c], Ag + (size_t)r * lda + k0 + c);
        }
#pragma unroll
        for (int i = 0; i < 2; i++) {
            int ch = tid + 256 * i;
            int r = ch >> 4, c = (ch & 15) * 8;
            cp_async16(&sm.Bs[s][r][c], Bg + (size_t)(k0 + r) * ldb + c);
        }
        cp_commit();
    };

    const int nt = K / 32;
    stage(0, 0);
    for (int t = 0; t < nt; t++) {
        if (t + 1 < nt) {
            stage((t + 1) & 1, (t + 1) * 32);
            asm volatile("cp.async.wait_group 1;");
        } else {
            asm volatile("cp.async.wait_group 0;");
        }
        __syncthreads();
        const int s = t & 1;
#pragma unroll
        for (int kk = 0; kk < 32; kk += 16) {
            HFragA fa[4];
            HFragB fb[2];
#pragma unroll
            for (int i = 0; i < 4; i++)
                wmma::load_matrix_sync(fa[i], &sm.As[s][wm * 64 + i * 16][kk], 40);
#pragma unroll
            for (int j = 0; j < 2; j++)
                wmma::load_matrix_sync(fb[j], &sm.Bs[s][kk][wn * 32 + j * 16], 136);
#pragma unroll
            for (int i = 0; i < 4; i++)
#pragma unroll
                for (int j = 0; j < 2; j++)
                    wmma::mma_sync(acc[i][j], fa[i], fb[j], acc[i][j]);
        }
        __syncthreads();
    }
#pragma unroll
    for (int i = 0; i < 4; i++)
#pragma unroll
        for (int j = 0; j < 2; j++)
            wmma::store_matrix_sync(
                C + (size_t)(brow * 128 + wm * 64 + i * 16) * ldc + bcol * 128 + wn * 32 + j * 16,
                acc[i][j], ldc, wmma::mem_row_major);
}

// ---------------------------------------------------------------------------
// Flash attention (causal, GQA) — fp16 tensor path, fp32 softmax/accum.
// One CTA = 64 query rows x 1 head, 4 warps x 16 rows.
// mma.m16n8k16.f16: A frags {rows lr/lr+8, k 2lc/2lc+1 (+8)}, B frags
// {k 2lc,2lc+1 (+8), col lr} -> contiguous half-pairs in Ks (natural) and
// V16T (pre-transposed). All smem row strides = 16 mod 128 B: conflict-free.
// ---------------------------------------------------------------------------
struct FlashSmem {
    __half Ks[64][136];    // row stride 272B
    __half Vt[128][72];    // row stride 144B
    __half Ps[64][72];     // row stride 144B (per-warp strips)
};

__global__ __launch_bounds__(128)
void flash_attn(const float* __restrict__ Q, const __half* __restrict__ K16,
                const __half* __restrict__ V16T, __half* __restrict__ O16)
{
    extern __shared__ char smem_raw[];
    FlashSmem& sm = *reinterpret_cast<FlashSmem*>(smem_raw);

    const int h   = blockIdx.x;
    const int qb  = gridDim.y - 1 - blockIdx.y;   // big workloads first
    const int kvh = h >> 2;
    const int warp = threadIdx.x >> 5;
    const int lane = threadIdx.x & 31;
    const int lr = lane >> 2;   // 0..7
    const int lc = lane & 3;    // 0..3

    // --- Q fragments (scale folded), packed fp16, registers all kernel ---
    unsigned qa[8][4];
    {
        const float scale = 0.08838834764831845f;   // 1/sqrt(128)
        const float* Qb = Q + (size_t)(qb * 64 + warp * 16) * DMODEL + h * HD;
#pragma unroll
        for (int kt = 0; kt < 8; kt++) {
            int c0 = kt * 16 + 2 * lc;
            qa[kt][0] = packh2(Qb[(size_t)lr * DMODEL + c0] * scale,
                               Qb[(size_t)lr * DMODEL + c0 + 1] * scale);
            qa[kt][1] = packh2(Qb[(size_t)(lr + 8) * DMODEL + c0] * scale,
                               Qb[(size_t)(lr + 8) * DMODEL + c0 + 1] * scale);
            qa[kt][2] = packh2(Qb[(size_t)lr * DMODEL + c0 + 8] * scale,
                               Qb[(size_t)lr * DMODEL + c0 + 9] * scale);
            qa[kt][3] = packh2(Qb[(size_t)(lr + 8) * DMODEL + c0 + 8] * scale,
                               Qb[(size_t)(lr + 8) * DMODEL + c0 + 9] * scale);
        }
    }

    float oacc[16][4];
#pragma unroll
    for (int j = 0; j < 16; j++)
#pragma unroll
        for (int e = 0; e < 4; e++) oacc[j][e] = 0.0f;
    float m0 = -1e30f, m1 = -1e30f, l0 = 0.0f, l1 = 0.0f;

    for (int kb = 0; kb <= qb; kb++) {
        __syncthreads();
        {
            // Ks: 64 rows x 256B (16 chunks); Vt: 128 rows x 128B (8 chunks)
            const __half* Kt = K16 + (size_t)(kb * 64) * KVD + kvh * HD;
            const __half* Vg = V16T + (size_t)(kvh * HD) * SEQ + kb * 64;
#pragma unroll
            for (int i = 0; i < 8; i++) {
                int ch = threadIdx.x + 128 * i;        // 0..1023
                int kr = ch >> 4, kj = ch & 15;
                cp_async16(&sm.Ks[kr][kj * 8], Kt + (size_t)kr * KVD + kj * 8);
                int vr = ch >> 3, vj = ch & 7;
                cp_async16(&sm.Vt[vr][vj * 8], Vg + (size_t)vr * SEQ + vj * 8);
            }
            cp_commit();
            asm volatile("cp.async.wait_group 0;");
        }
        __syncthreads();

        // ---- S = (Q*scale) @ K^T  [16 x 64] per warp ----
        float sacc[8][4];
#pragma unroll
        for (int j = 0; j < 8; j++)
#pragma unroll
            for (int e = 0; e < 4; e++) sacc[j][e] = 0.0f;
#pragma unroll
        for (int kt = 0; kt < 8; kt++) {
            const int c0 = kt * 16 + 2 * lc;
#pragma unroll
            for (int j = 0; j < 8; j++) {
                unsigned b0 = *reinterpret_cast<const unsigned*>(&sm.Ks[j * 8 + lr][c0]);
                unsigned b1 = *reinterpret_cast<const unsigned*>(&sm.Ks[j * 8 + lr][c0 + 8]);
                mma_f16(sacc[j], qa[kt], b0, b1);
            }
        }

        // ---- causal mask (diagonal block only) ----
        if (kb == qb) {
            const int r0 = warp * 16 + lr, r1 = r0 + 8;
#pragma unroll
            for (int j = 0; j < 8; j++) {
                int c0 = j * 8 + lc * 2;
                if (c0     > r0) sacc[j][0] = -1e30f;
                if (c0 + 1 > r0) sacc[j][1] = -1e30f;
                if (c0     > r1) sacc[j][2] = -1e30f;
                if (c0 + 1 > r1) sacc[j][3] = -1e30f;
            }
        }

        // ---- online softmax (fp32) ----
        float mx0 = -1e30f, mx1 = -1e30f;
#pragma unroll
        for (int j = 0; j < 8; j++) {
            mx0 = fmaxf(mx0, fmaxf(sacc[j][0], sacc[j][1]));
            mx1 = fmaxf(mx1, fmaxf(sacc[j][2], sacc[j][3]));
        }
        mx0 = fmaxf(mx0, __shfl_xor_sync(0xffffffffu, mx0, 1));
        mx0 = fmaxf(mx0, __shfl_xor_sync(0xffffffffu, mx0, 2));
        mx1 = fmaxf(mx1, __shfl_xor_sync(0xffffffffu, mx1, 1));
        mx1 = fmaxf(mx1, __shfl_xor_sync(0xffffffffu, mx1, 2));
        const float mn0 = fmaxf(m0, mx0), mn1 = fmaxf(m1, mx1);
        const float al0 = __expf(m0 - mn0), al1 = __expf(m1 - mn1);
        m0 = mn0; m1 = mn1;

        float s0 = 0.0f, s1 = 0.0f;
        const int prow = warp * 16 + lr;
#pragma unroll
        for (int j = 0; j < 8; j++) {
            float p0 = __expf(sacc[j][0] - m0);
            float p1 = __expf(sacc[j][1] - m0);
            float p2 = __expf(sacc[j][2] - m1);
            float p3 = __expf(sacc[j][3] - m1);
            s0 += p0 + p1;
            s1 += p2 + p3;
            *reinterpret_cast<unsigned*>(&sm.Ps[prow][j * 8 + lc * 2])     = packh2(p0, p1);
            *reinterpret_cast<unsigned*>(&sm.Ps[prow + 8][j * 8 + lc * 2]) = packh2(p2, p3);
        }
        s0 += __shfl_xor_sync(0xffffffffu, s0, 1);
        s0 += __shfl_xor_sync(0xffffffffu, s0, 2);
        s1 += __shfl_xor_sync(0xffffffffu, s1, 1);
        s1 += __shfl_xor_sync(0xffffffffu, s1, 2);
        l0 = l0 * al0 + s0;
        l1 = l1 * al1 + s1;

#pragma unroll
        for (int j = 0; j < 16; j++) {
            oacc[j][0] *= al0; oacc[j][1] *= al0;
            oacc[j][2] *= al1; oacc[j][3] *= al1;
        }
        __syncwarp();

        // ---- O += P @ V  (A from Ps strip, B from Vt) ----
#pragma unroll
        for (int kt = 0; kt < 4; kt++) {
            const int c0 = kt * 16 + 2 * lc;
            unsigned pa[4];
            pa[0] = *reinterpret_cast<const unsigned*>(&sm.Ps[warp * 16 + lr][c0]);
            pa[1] = *reinterpret_cast<const unsigned*>(&sm.Ps[warp * 16 + lr + 8][c0]);
            pa[2] = *reinterpret_cast<const unsigned*>(&sm.Ps[warp * 16 + lr][c0 + 8]);
            pa[3] = *reinterpret_cast<const unsigned*>(&sm.Ps[warp * 16 + lr + 8][c0 + 8]);
#pragma unroll
            for (int j = 0; j < 16; j++) {
                unsigned b0 = *reinterpret_cast<const unsigned*>(&sm.Vt[j * 8 + lr][c0]);
                unsigned b1 = *reinterpret_cast<const unsigned*>(&sm.Vt[j * 8 + lr][c0 + 8]);
                mma_f16(oacc[j], pa, b0, b1);
            }
        }
    }

    // ---- epilogue: normalize, write O directly in fp16 ----
    const float r0 = 1.0f / l0, r1 = 1.0f / l1;
    __half* Ob = O16 + (size_t)(qb * 64 + warp * 16) * DMODEL + h * HD;
#pragma unroll
    for (int j = 0; j < 16; j++) {
        *reinterpret_cast<unsigned*>(&Ob[(size_t)lr * DMODEL + j * 8 + lc * 2]) =
            packh2(oacc[j][0] * r0, oacc[j][1] * r0);
        *reinterpret_cast<unsigned*>(&Ob[(size_t)(lr + 8) * DMODEL + j * 8 + lc * 2]) =
            packh2(oacc[j][2] * r1, oacc[j][3] * r1);
    }
}

// ---------------------------------------------------------------------------
// RoPE: Q fp32 in-place; K fp32 -> fp16 out.
// ---------------------------------------------------------------------------
__global__ void rope_q(float* __restrict__ X, int total)
{
    int idx = blockIdx.x * blockDim.x + threadIdx.x;
    if (idx >= total) return;
    int p = idx & 63;
    int t = idx >> 6;
    int h = t % NHEAD;
    int s = t / NHEAD;
    float inv = exp2f(-(float)p * (18.931568569324174f / 64.0f));
    float sv, cv;
    sincosf((float)s * inv, &sv, &cv);
    float* q = X + (size_t)s * DMODEL + h * HD + 2 * p;
    float x0 = q[0], x1 = q[1];
    q[0] = x0 * cv - x1 * sv;
    q[1] = x0 * sv + x1 * cv;
}

__global__ void rope_k16(const float* __restrict__ Kin, __half* __restrict__ Kout, int total)
{
    int idx = blockIdx.x * blockDim.x + threadIdx.x;
    if (idx >= total) return;
    int p = idx & 63;
    int t = idx >> 6;
    int h = t % NKV;
    int s = t / NKV;
    float inv = exp2f(-(float)p * (18.931568569324174f / 64.0f));
    float sv, cv;
    sincosf((float)s * inv, &sv, &cv);
    const float* k = Kin + (size_t)s * KVD + h * HD + 2 * p;
    float x0 = k[0], x1 = k[1];
    *reinterpret_cast<unsigned*>(Kout + (size_t)s * KVD + h * HD + 2 * p) =
        packh2(x0 * cv - x1 * sv, x0 * sv + x1 * cv);
}

// ---------------------------------------------------------------------------
// Launch
// ---------------------------------------------------------------------------
extern "C" void kernel_launch(void* const* d_in, const int* in_sizes, int n_in,
                              void* d_out, int out_size)
{
    const float* x  = (const float*)d_in[0];
    const float* Wq = (const float*)d_in[1];
    const float* Wk = (const float*)d_in[2];
    const float* Wv = (const float*)d_in[3];
    const float* Wo = (const float*)d_in[4];
    float* out = (float*)d_out;

    float *Q, *K, *V;
    __half *K16, *V16T, *x16, *O16, *Wq16, *Wk16, *Wv16, *Wo16;
    cudaGetSymbolAddress((void**)&Q, g_Q);
    cudaGetSymbolAddress((void**)&K, g_K);
    cudaGetSymbolAddress((void**)&V, g_V);
    cudaGetSymbolAddress((void**)&K16, g_K16);
    cudaGetSymbolAddress((void**)&V16T, g_V16T);
    cudaGetSymbolAddress((void**)&x16, g_x16);
    cudaGetSymbolAddress((void**)&O16, g_O16);
    cudaGetSymbolAddress((void**)&Wq16, g_Wq16);
    cudaGetSymbolAddress((void**)&Wk16, g_Wk16);
    cudaGetSymbolAddress((void**)&Wv16, g_Wv16);
    cudaGetSymbolAddress((void**)&Wo16, g_Wo16);

    cudaFuncSetAttribute(gemm_f16_nn, cudaFuncAttributeMaxDynamicSharedMemorySize,
                         (int)sizeof(GemmHSmem));
    cudaFuncSetAttribute(flash_attn, cudaFuncAttributeMaxDynamicSharedMemorySize,
                         (int)sizeof(FlashSmem));

    // fp32 -> fp16 conversions (x and weights)
    {
        const int nx = SEQ * DMODEL;
        const int nq = DMODEL * DMODEL;
        const int nk = DMODEL * KVD;
        f32_to_f16<<<(nx / 8 + 255) / 256, 256>>>(x,  x16,  nx);
        f32_to_f16<<<(nq / 8 + 255) / 256, 256>>>(Wq, Wq16, nq);
        f32_to_f16<<<(nk / 8 + 255) / 256, 256>>>(Wk, Wk16, nk);
        f32_to_f16<<<(nk / 8 + 255) / 256, 256>>>(Wv, Wv16, nk);
        f32_to_f16<<<(nq / 8 + 255) / 256, 256>>>(Wo, Wo16, nq);
    }

    // QKV projections (fp16 HMMA, fp32 accumulate)
    gemm_f16_nn<<<dim3(DMODEL / 128, SEQ / 128), 256, sizeof(GemmHSmem)>>>(
        x16, Wq16, Q, DMODEL, DMODEL, DMODEL, DMODEL);
    gemm_f16_nn<<<dim3(KVD / 128, SEQ / 128), 256, sizeof(GemmHSmem)>>>(
        x16, Wk16, K, DMODEL, DMODEL, KVD, KVD);
    gemm_f16_nn<<<dim3(KVD / 128, SEQ / 128), 256, sizeof(GemmHSmem)>>>(
        x16, Wv16, V, DMODEL, DMODEL, KVD, KVD);

    // RoPE (Q fp32 in-place, K -> fp16) + V -> fp16 transposed
    {
        int totq = SEQ * NHEAD * (HD / 2);
        rope_q<<<(totq + 255) / 256, 256>>>(Q, totq);
        int totk = SEQ * NKV * (HD / 2);
        rope_k16<<<(totk + 255) / 256, 256>>>(K, K16, totk);
        v_transp16<<<dim3(KVD / 32, SEQ / 32), dim3(32, 8)>>>(V, V16T);
    }

    // Fused causal flash attention (fp16 tensor path) -> O16
    flash_attn<<<dim3(NHEAD, SEQ / 64), 128, sizeof(FlashSmem)>>>(Q, K16, V16T, O16);

    // Output projection
    gemm_f16_nn<<<dim3(DMODEL / 128, SEQ / 128), 256, sizeof(GemmHSmem)>>>(
        O16, Wo16, out, DMODEL, DMODEL, DMODEL, DMODEL);
}